// round 3
// baseline (speedup 1.0000x reference)
#include <cuda_runtime.h>
#include <math.h>

#define B_ 8
#define N_ 2048
#define M_ 2048
#define D_ 256
#define EPS_ 1e-8f

// Scratch for precomputed norms (allocation-free: __device__ globals)
__device__ float g_src_norm[B_ * N_];
__device__ float g_dst_norm[B_ * M_];

// ---------------------------------------------------------------------------
// Kernel 1: row L2 norms for src and dst. One warp per row.
// ---------------------------------------------------------------------------
__global__ void norms_kernel(const float* __restrict__ src,
                             const float* __restrict__ dst) {
    int gwarp = (blockIdx.x * blockDim.x + threadIdx.x) >> 5;
    int lane = threadIdx.x & 31;
    const int total = B_ * N_ + B_ * M_;
    if (gwarp >= total) return;

    const float* base;
    float* outp;
    int row;
    if (gwarp < B_ * N_) { base = src; row = gwarp;            outp = g_src_norm; }
    else                 { base = dst; row = gwarp - B_ * N_;  outp = g_dst_norm; }

    const float* p = base + (size_t)row * D_;
    float s = 0.f;
    #pragma unroll
    for (int d = lane; d < D_; d += 32) {
        float v = p[d];
        s = fmaf(v, v, s);
    }
    #pragma unroll
    for (int o = 16; o > 0; o >>= 1) s += __shfl_xor_sync(0xffffffffu, s, o);
    if (lane == 0) outp[row] = sqrtf(s);
}

// ---------------------------------------------------------------------------
// Kernel 2: fused cosine-GEMM + argmax + gather.
// Block = 64 src rows (one batch). Loops over M in 64-wide tiles, D in 64
// chunks. 256 threads, 4x4 micro-tile. Running (max, idx) per thread, final
// 16-way reduce per row with first-occurrence tie-break (jnp.argmax semantics).
// ---------------------------------------------------------------------------
__global__ __launch_bounds__(256, 2)
void match_kernel(const float* __restrict__ src,
                  const float* __restrict__ dst,
                  const float* __restrict__ pts,
                  float* __restrict__ out) {
    const int b  = blockIdx.y;
    const int n0 = blockIdx.x * 64;
    const int tid = threadIdx.x;
    const int tx = tid & 15;   // column group
    const int ty = tid >> 4;   // row group

    __shared__ float As[64][65];
    __shared__ float Bs[64][65];
    __shared__ float red_val[64][17];
    __shared__ int   red_idx[64][17];

    const float* srcB = src + (size_t)b * N_ * D_;
    const float* dstB = dst + (size_t)b * M_ * D_;

    float bestv[4];
    int   besti[4];
    float xn[4];
    #pragma unroll
    for (int i = 0; i < 4; i++) {
        bestv[i] = -1e30f;
        besti[i] = 0;
        xn[i] = g_src_norm[b * N_ + n0 + ty * 4 + i];
    }

    for (int m0 = 0; m0 < M_; m0 += 64) {
        float acc[4][4];
        #pragma unroll
        for (int i = 0; i < 4; i++)
            #pragma unroll
            for (int j = 0; j < 4; j++) acc[i][j] = 0.f;

        for (int d0 = 0; d0 < D_; d0 += 64) {
            // Load 64x64 tiles of A (src rows) and B (dst rows).
            // 1024 float4 per tile, 256 threads -> 4 float4 each.
            #pragma unroll
            for (int i = 0; i < 4; i++) {
                int e   = tid + i * 256;      // float4 index 0..1023
                int row = e >> 4;             // 16 float4 per row
                int c4  = (e & 15) << 2;
                float4 va = *(const float4*)(srcB + (size_t)(n0 + row) * D_ + d0 + c4);
                As[row][c4 + 0] = va.x; As[row][c4 + 1] = va.y;
                As[row][c4 + 2] = va.z; As[row][c4 + 3] = va.w;
                float4 vb = *(const float4*)(dstB + (size_t)(m0 + row) * D_ + d0 + c4);
                Bs[row][c4 + 0] = vb.x; Bs[row][c4 + 1] = vb.y;
                Bs[row][c4 + 2] = vb.z; Bs[row][c4 + 3] = vb.w;
            }
            __syncthreads();

            #pragma unroll 16
            for (int k = 0; k < 64; k++) {
                float a[4], bb[4];
                #pragma unroll
                for (int i = 0; i < 4; i++) a[i]  = As[ty * 4 + i][k];
                #pragma unroll
                for (int j = 0; j < 4; j++) bb[j] = Bs[tx * 4 + j][k];
                #pragma unroll
                for (int i = 0; i < 4; i++)
                    #pragma unroll
                    for (int j = 0; j < 4; j++)
                        acc[i][j] = fmaf(a[i], bb[j], acc[i][j]);
            }
            __syncthreads();
        }

        // Epilogue for this M tile: cosine + running argmax.
        #pragma unroll
        for (int j = 0; j < 4; j++) {
            int m = m0 + tx * 4 + j;
            float yn = g_dst_norm[b * M_ + m];
            #pragma unroll
            for (int i = 0; i < 4; i++) {
                float denom = fmaxf(xn[i] * yn, EPS_);
                float sim = acc[i][j] / denom;
                // strict > keeps the earliest index within this thread
                if (sim > bestv[i]) { bestv[i] = sim; besti[i] = m; }
            }
        }
    }

    // Cross-thread reduction: 16 column-group candidates per row.
    #pragma unroll
    for (int i = 0; i < 4; i++) {
        red_val[ty * 4 + i][tx] = bestv[i];
        red_idx[ty * 4 + i][tx] = besti[i];
    }
    __syncthreads();

    if (tid < 64) {
        float bv = -1e30f;
        int   bi = 0x7fffffff;
        #pragma unroll
        for (int t = 0; t < 16; t++) {
            float v = red_val[tid][t];
            int   id = red_idx[tid][t];
            if (v > bv || (v == bv && id < bi)) { bv = v; bi = id; }
        }
        int n = n0 + tid;
        size_t row = (size_t)b * N_ + n;
        // matched points [B, N, 2] at offset 0
        out[row * 2 + 0] = pts[((size_t)b * M_ + bi) * 2 + 0];
        out[row * 2 + 1] = pts[((size_t)b * M_ + bi) * 2 + 1];
        // confidence [B, N] after matched block
        out[(size_t)B_ * N_ * 2 + row] = bv;
    }
}

// ---------------------------------------------------------------------------
extern "C" void kernel_launch(void* const* d_in, const int* in_sizes, int n_in,
                              void* d_out, int out_size) {
    const float* desc_src   = (const float*)d_in[0];
    const float* desc_dst   = (const float*)d_in[1];
    const float* points_dst = (const float*)d_in[2];
    float* out = (float*)d_out;

    // Norms: one warp per row, 8 warps per block.
    const int total_rows = B_ * N_ + B_ * M_;
    const int warps_per_block = 8;
    int nblocks = (total_rows + warps_per_block - 1) / warps_per_block;
    norms_kernel<<<nblocks, warps_per_block * 32>>>(desc_src, desc_dst);

    dim3 grid(N_ / 64, B_);
    match_kernel<<<grid, 256>>>(desc_src, desc_dst, points_dst, out);
}

// round 6
// speedup vs baseline: 1.7802x; 1.7802x over previous
#include <cuda_runtime.h>
#include <math.h>

#define B_ 8
#define N_ 2048
#define M_ 2048
#define D_ 256
#define EPS_ 1e-8f

#define BM 128
#define BN 128
#define BK 16
#define TM 8
#define TN 8
#define NCHUNK (D_ / BK)

// Allocation-free scratch
__device__ float g_src_norm[B_ * N_];   // ||x|| for confidence rescale
__device__ float g_dst_inv[B_ * M_];    // 1/||y|| folded into the epilogue

// ---------------------------------------------------------------------------
// Kernel 1: row L2 norms. One warp per row. src -> norm, dst -> 1/norm.
// ---------------------------------------------------------------------------
__global__ void norms_kernel(const float* __restrict__ src,
                             const float* __restrict__ dst) {
    int gwarp = (blockIdx.x * blockDim.x + threadIdx.x) >> 5;
    int lane = threadIdx.x & 31;
    const int total = B_ * N_ + B_ * M_;
    if (gwarp >= total) return;

    bool is_src = gwarp < B_ * N_;
    int row = is_src ? gwarp : gwarp - B_ * N_;
    const float* p = (is_src ? src : dst) + (size_t)row * D_;

    float s = 0.f;
    #pragma unroll
    for (int d = lane; d < D_; d += 32) {
        float v = p[d];
        s = fmaf(v, v, s);
    }
    #pragma unroll
    for (int o = 16; o > 0; o >>= 1) s += __shfl_xor_sync(0xffffffffu, s, o);
    if (lane == 0) {
        float nrm = sqrtf(s);
        if (is_src) g_src_norm[row] = nrm;
        else        g_dst_inv[row] = 1.0f / nrm;
    }
}

// ---------------------------------------------------------------------------
// Kernel 2: fused cosine-GEMM + argmax + gather.
// 128x128 block tile, 256 threads, 8x8 micro-tile, BK=16 double-buffered.
// Per-row argmax over t = xy * (1/||y||); confidence = t_best / ||x||.
// ---------------------------------------------------------------------------
__global__ __launch_bounds__(256, 1)
void match_kernel(const float* __restrict__ src,
                  const float* __restrict__ dst,
                  const float* __restrict__ pts,
                  float* __restrict__ out) {
    const int b  = blockIdx.y;
    const int n0 = blockIdx.x * BM;
    const int tid = threadIdx.x;
    const int tx = tid & 15;        // 16 column groups of 8
    const int ty = tid >> 4;        // 16 row groups of 8
    const int lr = tid >> 2;        // load row 0..63 (and +64)
    const int lc = (tid & 3) << 2;  // load col 0,4,8,12 within 16-wide chunk

    __shared__ union {
        struct { float A[2][BK][BM + 4]; float B[2][BK][BN + 4]; } t;
        struct { float val[BM][17]; int idx[BM][17]; } r;
    } sm;

    const float* srcB = src + (size_t)b * N_ * D_;
    const float* dstB = dst + (size_t)b * M_ * D_;

    float bestv[TM];
    int   besti[TM];
    #pragma unroll
    for (int i = 0; i < TM; i++) { bestv[i] = -1e30f; besti[i] = 0; }

    for (int m0 = 0; m0 < M_; m0 += BN) {
        float acc[TM][TN];
        #pragma unroll
        for (int i = 0; i < TM; i++)
            #pragma unroll
            for (int j = 0; j < TN; j++) acc[i][j] = 0.f;

        // --- preload chunk 0 into buffer 0 ---
        float4 va0 = *(const float4*)(srcB + (n0 + lr) * D_ + lc);
        float4 va1 = *(const float4*)(srcB + (n0 + lr + 64) * D_ + lc);
        float4 vb0 = *(const float4*)(dstB + (m0 + lr) * D_ + lc);
        float4 vb1 = *(const float4*)(dstB + (m0 + lr + 64) * D_ + lc);
        sm.t.A[0][lc + 0][lr] = va0.x; sm.t.A[0][lc + 1][lr] = va0.y;
        sm.t.A[0][lc + 2][lr] = va0.z; sm.t.A[0][lc + 3][lr] = va0.w;
        sm.t.A[0][lc + 0][lr + 64] = va1.x; sm.t.A[0][lc + 1][lr + 64] = va1.y;
        sm.t.A[0][lc + 2][lr + 64] = va1.z; sm.t.A[0][lc + 3][lr + 64] = va1.w;
        sm.t.B[0][lc + 0][lr] = vb0.x; sm.t.B[0][lc + 1][lr] = vb0.y;
        sm.t.B[0][lc + 2][lr] = vb0.z; sm.t.B[0][lc + 3][lr] = vb0.w;
        sm.t.B[0][lc + 0][lr + 64] = vb1.x; sm.t.B[0][lc + 1][lr + 64] = vb1.y;
        sm.t.B[0][lc + 2][lr + 64] = vb1.z; sm.t.B[0][lc + 3][lr + 64] = vb1.w;
        __syncthreads();

        for (int c = 0; c < NCHUNK; ++c) {
            const int cur = c & 1;
            // prefetch next chunk into registers (overlaps with compute)
            if (c + 1 < NCHUNK) {
                const int d0 = (c + 1) * BK;
                va0 = *(const float4*)(srcB + (n0 + lr) * D_ + d0 + lc);
                va1 = *(const float4*)(srcB + (n0 + lr + 64) * D_ + d0 + lc);
                vb0 = *(const float4*)(dstB + (m0 + lr) * D_ + d0 + lc);
                vb1 = *(const float4*)(dstB + (m0 + lr + 64) * D_ + d0 + lc);
            }

            #pragma unroll 8
            for (int k = 0; k < BK; ++k) {
                float4 a0 = *(const float4*)&sm.t.A[cur][k][ty * TM];
                float4 a1 = *(const float4*)&sm.t.A[cur][k][ty * TM + 4];
                float4 b0 = *(const float4*)&sm.t.B[cur][k][tx * TN];
                float4 b1 = *(const float4*)&sm.t.B[cur][k][tx * TN + 4];
                float a[TM] = {a0.x, a0.y, a0.z, a0.w, a1.x, a1.y, a1.z, a1.w};
                float bb[TN] = {b0.x, b0.y, b0.z, b0.w, b1.x, b1.y, b1.z, b1.w};
                #pragma unroll
                for (int i = 0; i < TM; i++)
                    #pragma unroll
                    for (int j = 0; j < TN; j++)
                        acc[i][j] = fmaf(a[i], bb[j], acc[i][j]);
            }

            if (c + 1 < NCHUNK) {
                const int nb = cur ^ 1;
                sm.t.A[nb][lc + 0][lr] = va0.x; sm.t.A[nb][lc + 1][lr] = va0.y;
                sm.t.A[nb][lc + 2][lr] = va0.z; sm.t.A[nb][lc + 3][lr] = va0.w;
                sm.t.A[nb][lc + 0][lr + 64] = va1.x; sm.t.A[nb][lc + 1][lr + 64] = va1.y;
                sm.t.A[nb][lc + 2][lr + 64] = va1.z; sm.t.A[nb][lc + 3][lr + 64] = va1.w;
                sm.t.B[nb][lc + 0][lr] = vb0.x; sm.t.B[nb][lc + 1][lr] = vb0.y;
                sm.t.B[nb][lc + 2][lr] = vb0.z; sm.t.B[nb][lc + 3][lr] = vb0.w;
                sm.t.B[nb][lc + 0][lr + 64] = vb1.x; sm.t.B[nb][lc + 1][lr + 64] = vb1.y;
                sm.t.B[nb][lc + 2][lr + 64] = vb1.z; sm.t.B[nb][lc + 3][lr + 64] = vb1.w;
            }
            __syncthreads();
        }

        // --- epilogue: scale by 1/||y||, running argmax (ascending m) ---
        #pragma unroll
        for (int j = 0; j < TN; ++j) {
            int m = m0 + tx * TN + j;
            float yin = g_dst_inv[b * M_ + m];
            #pragma unroll
            for (int i = 0; i < TM; ++i) {
                float t = acc[i][j] * yin;
                if (t > bestv[i]) { bestv[i] = t; besti[i] = m; }
            }
        }
    }

    // Cross-thread reduction: 16 candidates per row, lowest index wins ties.
    #pragma unroll
    for (int i = 0; i < TM; ++i) {
        sm.r.val[ty * TM + i][tx] = bestv[i];
        sm.r.idx[ty * TM + i][tx] = besti[i];
    }
    __syncthreads();

    if (tid < BM) {
        float bv = -1e30f;
        int   bi = 0x7fffffff;
        #pragma unroll
        for (int t = 0; t < 16; t++) {
            float v = sm.r.val[tid][t];
            int  id = sm.r.idx[tid][t];
            if (v > bv || (v == bv && id < bi)) { bv = v; bi = id; }
        }
        int n = n0 + tid;
        size_t row = (size_t)b * N_ + n;
        out[row * 2 + 0] = pts[((size_t)b * M_ + bi) * 2 + 0];
        out[row * 2 + 1] = pts[((size_t)b * M_ + bi) * 2 + 1];
        out[(size_t)B_ * N_ * 2 + row] = bv / g_src_norm[b * N_ + n];
    }
}

// ---------------------------------------------------------------------------
extern "C" void kernel_launch(void* const* d_in, const int* in_sizes, int n_in,
                              void* d_out, int out_size) {
    const float* desc_src   = (const float*)d_in[0];
    const float* desc_dst   = (const float*)d_in[1];
    const float* points_dst = (const float*)d_in[2];
    float* out = (float*)d_out;

    const int total_rows = B_ * N_ + B_ * M_;
    const int warps_per_block = 8;
    int nblocks = (total_rows + warps_per_block - 1) / warps_per_block;
    norms_kernel<<<nblocks, warps_per_block * 32>>>(desc_src, desc_dst);

    dim3 grid(N_ / BM, B_);
    match_kernel<<<grid, 256>>>(desc_src, desc_dst, points_dst, out);
}

// round 10
// speedup vs baseline: 3.0247x; 1.6991x over previous
#include <cuda_runtime.h>
#include <cuda_bf16.h>
#include <cstdint>
#include <math.h>

#define B_ 8
#define N_ 2048
#define M_ 2048
#define D_ 256
#define KS_ 768                  // 3 bf16 limbs x 256
#define KC 64                    // bf16 k per chunk (128-byte rows, SW128)
#define NCHUNK (KS_ / KC)        // 12 B-chunks per tile (limb-major: y0,y1,y2)
#define NTILES (M_ / 128)        // 16
#define TOTC (NTILES * NCHUNK)   // 192 chunk steps
#define THREADS 256

#define A_OFF 0
#define B_OFF 196608             // 12 chunks * 16384
#define SMEM_BYTES (196608 + 32768)

// Split-bf16 operands (pre-normalized rows), limbs contiguous [x0|x1|x2]
__device__ __nv_bfloat16 gA[(size_t)B_ * N_ * KS_];
__device__ __nv_bfloat16 gBt[(size_t)B_ * M_ * KS_];

#define SWZ(x) ((x) ^ (((x) >> 3) & 0x70))

__device__ __forceinline__ uint32_t smem_u32(const void* p) {
    uint32_t a;
    asm("{ .reg .u64 t; cvta.to.shared.u64 t, %1; cvt.u32.u64 %0, t; }"
        : "=r"(a) : "l"(p));
    return a;
}
__device__ __forceinline__ void cp_async16(uint32_t dst, const void* src) {
    asm volatile("cp.async.cg.shared.global [%0], [%1], 16;"
                 :: "r"(dst), "l"(src) : "memory");
}
__device__ __forceinline__ void cp_commit() {
    asm volatile("cp.async.commit_group;" ::: "memory");
}
template <int N>
__device__ __forceinline__ void cp_wait() {
    asm volatile("cp.async.wait_group %0;" :: "n"(N) : "memory");
}
// Non-trans ldmatrix for BOTH operands (A row-major k-contig, B n-major
// k-contig => NT pair for mma .row.col). Verified in R9: layout is correct.
__device__ __forceinline__ void ldm_x4(uint32_t* r, uint32_t addr) {
    asm volatile("ldmatrix.sync.aligned.m8n8.x4.shared.b16 {%0,%1,%2,%3}, [%4];"
                 : "=r"(r[0]), "=r"(r[1]), "=r"(r[2]), "=r"(r[3]) : "r"(addr));
}
__device__ __forceinline__ void mma16816(float* d, const uint32_t* a,
                                         const uint32_t* b) {
    asm volatile(
        "mma.sync.aligned.m16n8k16.row.col.f32.bf16.bf16.f32 "
        "{%0,%1,%2,%3}, {%4,%5,%6,%7}, {%8,%9}, {%0,%1,%2,%3};"
        : "+f"(d[0]), "+f"(d[1]), "+f"(d[2]), "+f"(d[3])
        : "r"(a[0]), "r"(a[1]), "r"(a[2]), "r"(a[3]), "r"(b[0]), "r"(b[1]));
}

// ---------------------------------------------------------------------------
// Kernel 1: normalize rows, split fp32 -> 3 bf16 limbs. One warp per row.
// ---------------------------------------------------------------------------
__global__ void prep_kernel(const float* __restrict__ src,
                            const float* __restrict__ dst) {
    int gw = (blockIdx.x * blockDim.x + threadIdx.x) >> 5;
    int lane = threadIdx.x & 31;
    if (gw >= B_ * (N_ + M_)) return;
    bool is_src = gw < B_ * N_;
    int row = is_src ? gw : gw - B_ * N_;
    const float* p = (is_src ? src : dst) + (size_t)row * D_;
    __nv_bfloat16* o = (is_src ? gA : gBt) + (size_t)row * KS_;

    float4 v0 = ((const float4*)p)[lane * 2];
    float4 v1 = ((const float4*)p)[lane * 2 + 1];
    float x[8] = {v0.x, v0.y, v0.z, v0.w, v1.x, v1.y, v1.z, v1.w};
    float s = 0.f;
    #pragma unroll
    for (int i = 0; i < 8; i++) s = fmaf(x[i], x[i], s);
    #pragma unroll
    for (int o2 = 16; o2 > 0; o2 >>= 1) s += __shfl_xor_sync(0xffffffffu, s, o2);
    float scale = 1.0f / sqrtf(s);

    __align__(16) __nv_bfloat16 t0[8], t1[8], t2[8];
    #pragma unroll
    for (int i = 0; i < 8; i++) {
        float v = x[i] * scale;
        __nv_bfloat16 h0 = __float2bfloat16(v);
        float r = v - __bfloat162float(h0);
        __nv_bfloat16 h1 = __float2bfloat16(r);
        float r2 = r - __bfloat162float(h1);
        t0[i] = h0; t1[i] = h1; t2[i] = __float2bfloat16(r2);
    }
    ((uint4*)(o))[lane]       = *(uint4*)t0;
    ((uint4*)(o + 256))[lane] = *(uint4*)t1;
    ((uint4*)(o + 512))[lane] = *(uint4*)t2;
}

// ---------------------------------------------------------------------------
// Kernel 2: bf16 mma.sync GEMM with 6-pair limb product + argmax + gather.
// Pairs: x0y0, x1y0, x2y0, x0y1, x1y1, x0y2  (full fp32-grade product;
// dropped x1y2+x2y1+x2y2 ~1e-9). Per B chunk (lb,kc), A limbs la<3-lb.
// CTA: 128 src rows x all 2048 dst. A resident (192KB SW128), B double-buffered.
// ---------------------------------------------------------------------------
__global__ __launch_bounds__(THREADS, 1)
void match_mma_kernel(const float* __restrict__ pts, float* __restrict__ out) {
    extern __shared__ char smem[];
    const uint32_t sb = smem_u32(smem);
    const int tid = threadIdx.x;
    const int wid = tid >> 5;
    const int lane = tid & 31;
    const int b = blockIdx.y;
    const int n0 = blockIdx.x * 128;

    const int WM = (wid & 3) * 32;      // warp m-offset (src rows)
    const int WN = (wid >> 2) * 64;     // warp n-offset (dst cols)

    const __nv_bfloat16* gArow = gA + ((size_t)b * N_ + n0) * KS_;
    const __nv_bfloat16* gBb   = gBt + (size_t)b * M_ * KS_;

    // ---- prologue: A resident load (group 0), B chunks 0,1 (groups 1,2) ----
    #pragma unroll 4
    for (int i = 0; i < 48; ++i) {
        int idx = tid + i * 256;
        int c = idx >> 10, rem = idx & 1023, r = rem >> 3, q = rem & 7;
        cp_async16(sb + A_OFF + c * 16384 + SWZ(r * 128 + q * 16),
                   (const char*)(gArow + (size_t)r * KS_ + c * KC) + q * 16);
    }
    cp_commit();
    #pragma unroll
    for (int pc = 0; pc < 2; ++pc) {
        #pragma unroll
        for (int i = 0; i < 4; ++i) {
            int idx = tid + i * 256;
            int r = idx >> 3, q = idx & 7;
            cp_async16(sb + B_OFF + pc * 16384 + SWZ(r * 128 + q * 16),
                       (const char*)(gBb + (size_t)r * KS_ + pc * KC) + q * 16);
        }
        cp_commit();
    }

    // per-thread ldmatrix lane addressing (non-trans, NT pattern)
    const int ra  = (lane & 7) + ((lane >> 3) & 1) * 8;   // A row within 16
    const int kba = (lane >> 4) * 16;                     // A k-half bytes
    const int nb  = (lane & 7) + ((lane >> 4) & 1) * 8;   // B n-row within 16
    const int kbb = ((lane >> 3) & 1) * 16;               // B k-half bytes

    float acc[2][8][4];
    #pragma unroll
    for (int f = 0; f < 2; ++f)
        #pragma unroll
        for (int nf = 0; nf < 8; ++nf)
            #pragma unroll
            for (int k = 0; k < 4; ++k) acc[f][nf][k] = 0.f;

    float bestv[4] = {-1e30f, -1e30f, -1e30f, -1e30f};
    int   besti[4] = {0, 0, 0, 0};

    for (int C = 0; C < TOTC; ++C) {
        const int t = C / NCHUNK, c = C % NCHUNK, buf = C & 1;
        if (C == TOTC - 1) cp_wait<0>(); else cp_wait<1>();
        __syncthreads();

        // ---- compute: B chunk (lb, kc) vs A limbs la = 0..(2-lb) ----
        const uint32_t bbase = sb + B_OFF + buf * 16384;
        const int lb = c >> 2;          // B limb (0,1,2)
        const int kc = c & 3;           // k-chunk within the 256-wide limb
        const int nla = 3 - lb;         // number of A limbs paired with lb
        #pragma unroll
        for (int s = 0; s < 4; ++s) {
            uint32_t bf[4][4];
            #pragma unroll
            for (int p = 0; p < 4; ++p)
                ldm_x4(bf[p], bbase + SWZ((WN + p * 16 + nb) * 128 + s * 32 + kbb));
            #pragma unroll
            for (int la = 0; la < 3; ++la) {
                if (la >= nla) break;
                const uint32_t abase = sb + A_OFF + (la * 4 + kc) * 16384;
                uint32_t a[2][4];
                #pragma unroll
                for (int f = 0; f < 2; ++f)
                    ldm_x4(a[f], abase + SWZ((WM + f * 16 + ra) * 128 + s * 32 + kba));
                #pragma unroll
                for (int f = 0; f < 2; ++f)
                    #pragma unroll
                    for (int nf = 0; nf < 8; ++nf)
                        mma16816(acc[f][nf], a[f], &bf[nf >> 1][(nf & 1) * 2]);
            }
        }

        // ---- tile epilogue: fold acc into running argmax, reset acc ----
        if (c == NCHUNK - 1) {
            #pragma unroll
            for (int x = 0; x < 4; ++x) {
                const int f = x >> 1, hi = x & 1;
                float bv = bestv[x]; int bi = besti[x];
                #pragma unroll
                for (int nf = 0; nf < 8; ++nf) {
                    int nbase = t * 128 + WN + nf * 8 + (lane & 3) * 2;
                    float v0 = acc[f][nf][hi * 2];
                    float v1 = acc[f][nf][hi * 2 + 1];
                    if (v0 > bv) { bv = v0; bi = nbase; }
                    if (v1 > bv) { bv = v1; bi = nbase + 1; }
                    acc[f][nf][hi * 2] = 0.f;
                    acc[f][nf][hi * 2 + 1] = 0.f;
                }
                bestv[x] = bv; besti[x] = bi;
            }
        }
        __syncthreads();

        // ---- prefetch chunk C+2 into buffer buf ----
        if (C + 2 < TOTC) {
            const int C2 = C + 2, t2 = C2 / NCHUNK, c2 = C2 % NCHUNK;
            const __nv_bfloat16* gsrc = gBb + (size_t)(t2 * 128) * KS_ + c2 * KC;
            #pragma unroll
            for (int i = 0; i < 4; ++i) {
                int idx = tid + i * 256;
                int r = idx >> 3, q = idx & 7;
                cp_async16(sb + B_OFF + buf * 16384 + SWZ(r * 128 + q * 16),
                           (const char*)(gsrc + (size_t)r * KS_) + q * 16);
            }
            cp_commit();
        }
    }

    // ---- quad reduce: lanes sharing a row (lane^1, lane^2) ----
    #pragma unroll
    for (int x = 0; x < 4; ++x) {
        float v = bestv[x]; int i_ = besti[x];
        #pragma unroll
        for (int o = 1; o <= 2; o <<= 1) {
            float vo = __shfl_xor_sync(0xffffffffu, v, o);
            int   io = __shfl_xor_sync(0xffffffffu, i_, o);
            if (vo > v || (vo == v && io < i_)) { v = vo; i_ = io; }
        }
        bestv[x] = v; besti[x] = i_;
    }

    // ---- cross-warp-column combine via smem (reuse A region) ----
    float* sval = (float*)smem;          // [2][128]
    int*   sidx = (int*)(smem + 1024);   // [2][128]
    __syncthreads();
    if ((lane & 3) == 0) {
        const int col = wid >> 2;
        #pragma unroll
        for (int x = 0; x < 4; ++x) {
            int row = WM + (lane >> 2) + 8 * x;
            sval[col * 128 + row] = bestv[x];
            sidx[col * 128 + row] = besti[x];
        }
    }
    __syncthreads();
    if (tid < 128) {
        float v0 = sval[tid], v1 = sval[128 + tid];
        int   i0 = sidx[tid], i1 = sidx[128 + tid];
        float bv; int bi;
        if (v1 > v0 || (v1 == v0 && i1 < i0)) { bv = v1; bi = i1; }
        else                                  { bv = v0; bi = i0; }
        int n = n0 + tid;
        size_t row = (size_t)b * N_ + n;
        out[row * 2 + 0] = pts[((size_t)b * M_ + bi) * 2 + 0];
        out[row * 2 + 1] = pts[((size_t)b * M_ + bi) * 2 + 1];
        out[(size_t)B_ * N_ * 2 + row] = bv;
    }
}

// ---------------------------------------------------------------------------
extern "C" void kernel_launch(void* const* d_in, const int* in_sizes, int n_in,
                              void* d_out, int out_size) {
    const float* desc_src   = (const float*)d_in[0];
    const float* desc_dst   = (const float*)d_in[1];
    const float* points_dst = (const float*)d_in[2];
    float* out = (float*)d_out;

    int total_rows = B_ * (N_ + M_);
    int nblocks = (total_rows + 7) / 8;
    prep_kernel<<<nblocks, 256>>>(desc_src, desc_dst);

    cudaFuncSetAttribute(match_mma_kernel,
                         cudaFuncAttributeMaxDynamicSharedMemorySize, SMEM_BYTES);
    dim3 grid(N_ / 128, B_);
    match_mma_kernel<<<grid, THREADS, SMEM_BYTES>>>(points_dst, out);
}

// round 12
// speedup vs baseline: 5.2859x; 1.7476x over previous
#include <cuda_runtime.h>
#include <cuda_fp16.h>
#include <cstdint>
#include <math.h>

#define B_ 8
#define N_ 2048
#define M_ 2048
#define D_ 256
#define KS_ 512                  // 2 fp16 limbs x 256
#define KC 64                    // fp16 k per chunk (128-byte rows, SW128)
#define NCHUNK (KS_ / KC)        // 8 B-chunks per tile (limb-major: y0,y1)
#define NTILES (M_ / 128)        // 16
#define TOTC (NTILES * NCHUNK)   // 128 chunk steps
#define THREADS 256

#define A_OFF 0
#define B_OFF 131072             // 8 chunks * 16384
#define SMEM_BYTES (131072 + 32768)

#define CROSS_SCALE 2.44140625e-4f   // 2^-12

// Split-fp16 operands (pre-normalized rows): [x0 (256) | x1*2^12 (256)]
__device__ __half gA[(size_t)B_ * N_ * KS_];
__device__ __half gBt[(size_t)B_ * M_ * KS_];

#define SWZ(x) ((x) ^ (((x) >> 3) & 0x70))

__device__ __forceinline__ uint32_t smem_u32(const void* p) {
    uint32_t a;
    asm("{ .reg .u64 t; cvta.to.shared.u64 t, %1; cvt.u32.u64 %0, t; }"
        : "=r"(a) : "l"(p));
    return a;
}
__device__ __forceinline__ void cp_async16(uint32_t dst, const void* src) {
    asm volatile("cp.async.cg.shared.global [%0], [%1], 16;"
                 :: "r"(dst), "l"(src) : "memory");
}
__device__ __forceinline__ void cp_commit() {
    asm volatile("cp.async.commit_group;" ::: "memory");
}
template <int N>
__device__ __forceinline__ void cp_wait() {
    asm volatile("cp.async.wait_group %0;" :: "n"(N) : "memory");
}
// Non-trans ldmatrix for BOTH operands (A row-major k-contig, B n-major
// k-contig => NT pair for mma .row.col). Layout verified in R9/R10.
__device__ __forceinline__ void ldm_x4(uint32_t* r, uint32_t addr) {
    asm volatile("ldmatrix.sync.aligned.m8n8.x4.shared.b16 {%0,%1,%2,%3}, [%4];"
                 : "=r"(r[0]), "=r"(r[1]), "=r"(r[2]), "=r"(r[3]) : "r"(addr));
}
__device__ __forceinline__ void mma16816(float* d, const uint32_t* a,
                                         const uint32_t* b) {
    asm volatile(
        "mma.sync.aligned.m16n8k16.row.col.f32.f16.f16.f32 "
        "{%0,%1,%2,%3}, {%4,%5,%6,%7}, {%8,%9}, {%0,%1,%2,%3};"
        : "+f"(d[0]), "+f"(d[1]), "+f"(d[2]), "+f"(d[3])
        : "r"(a[0]), "r"(a[1]), "r"(a[2]), "r"(a[3]), "r"(b[0]), "r"(b[1]));
}

// ---------------------------------------------------------------------------
// Kernel 1: normalize rows, split fp32 -> 2 fp16 limbs (limb1 scaled 2^12).
// One warp per row.
// ---------------------------------------------------------------------------
__global__ void prep_kernel(const float* __restrict__ src,
                            const float* __restrict__ dst) {
    int gw = (blockIdx.x * blockDim.x + threadIdx.x) >> 5;
    int lane = threadIdx.x & 31;
    if (gw >= B_ * (N_ + M_)) return;
    bool is_src = gw < B_ * N_;
    int row = is_src ? gw : gw - B_ * N_;
    const float* p = (is_src ? src : dst) + (size_t)row * D_;
    __half* o = (is_src ? gA : gBt) + (size_t)row * KS_;

    float4 v0 = ((const float4*)p)[lane * 2];
    float4 v1 = ((const float4*)p)[lane * 2 + 1];
    float x[8] = {v0.x, v0.y, v0.z, v0.w, v1.x, v1.y, v1.z, v1.w};
    float s = 0.f;
    #pragma unroll
    for (int i = 0; i < 8; i++) s = fmaf(x[i], x[i], s);
    #pragma unroll
    for (int o2 = 16; o2 > 0; o2 >>= 1) s += __shfl_xor_sync(0xffffffffu, s, o2);
    float scale = 1.0f / sqrtf(s);

    __align__(16) __half t0[8], t1[8];
    #pragma unroll
    for (int i = 0; i < 8; i++) {
        float v = x[i] * scale;
        __half h0 = __float2half_rn(v);
        float r = v - __half2float(h0);
        t0[i] = h0;
        t1[i] = __float2half_rn(r * 4096.0f);   // 2^12 pre-scale
    }
    ((uint4*)(o))[lane]       = *(uint4*)t0;
    ((uint4*)(o + 256))[lane] = *(uint4*)t1;
}

// ---------------------------------------------------------------------------
// Kernel 2: fp16 mma.sync GEMM, 3 limb pairs (x0y0 -> main; x1y0, x0y1 ->
// cross, scaled 2^-12 in epilogue) + fused argmax + gather.
// CTA: 128 src rows x all 2048 dst. A resident (128KB SW128), B double-buffered.
// ---------------------------------------------------------------------------
__global__ __launch_bounds__(THREADS, 1)
void match_mma_kernel(const float* __restrict__ pts, float* __restrict__ out) {
    extern __shared__ char smem[];
    const uint32_t sb = smem_u32(smem);
    const int tid = threadIdx.x;
    const int wid = tid >> 5;
    const int lane = tid & 31;
    const int b = blockIdx.y;
    const int n0 = blockIdx.x * 128;

    const int WM = (wid & 3) * 32;      // warp m-offset (src rows)
    const int WN = (wid >> 2) * 64;     // warp n-offset (dst cols)

    const __half* gArow = gA + ((size_t)b * N_ + n0) * KS_;
    const __half* gBb   = gBt + (size_t)b * M_ * KS_;

    // ---- prologue: A resident load, B chunks 0,1 ----
    #pragma unroll 4
    for (int i = 0; i < 32; ++i) {
        int idx = tid + i * 256;
        int c = idx >> 10, rem = idx & 1023, r = rem >> 3, q = rem & 7;
        cp_async16(sb + A_OFF + c * 16384 + SWZ(r * 128 + q * 16),
                   (const char*)(gArow + (size_t)r * KS_ + c * KC) + q * 16);
    }
    cp_commit();
    #pragma unroll
    for (int pc = 0; pc < 2; ++pc) {
        #pragma unroll
        for (int i = 0; i < 4; ++i) {
            int idx = tid + i * 256;
            int r = idx >> 3, q = idx & 7;
            cp_async16(sb + B_OFF + pc * 16384 + SWZ(r * 128 + q * 16),
                       (const char*)(gBb + (size_t)r * KS_ + pc * KC) + q * 16);
        }
        cp_commit();
    }

    // per-thread ldmatrix lane addressing (non-trans, NT pattern)
    const int ra  = (lane & 7) + ((lane >> 3) & 1) * 8;   // A row within 16
    const int kba = (lane >> 4) * 16;                     // A k-half bytes
    const int nb  = (lane & 7) + ((lane >> 4) & 1) * 8;   // B n-row within 16
    const int kbb = ((lane >> 3) & 1) * 16;               // B k-half bytes

    float accm[2][8][4];   // x0*y0
    float accc[2][8][4];   // x1'*y0 + x0*y1'  (scale 2^-12)
    #pragma unroll
    for (int f = 0; f < 2; ++f)
        #pragma unroll
        for (int nf = 0; nf < 8; ++nf)
            #pragma unroll
            for (int k = 0; k < 4; ++k) { accm[f][nf][k] = 0.f; accc[f][nf][k] = 0.f; }

    float bestv[4] = {-1e30f, -1e30f, -1e30f, -1e30f};
    int   besti[4] = {0, 0, 0, 0};

    for (int C = 0; C < TOTC; ++C) {
        const int t = C / NCHUNK, c = C % NCHUNK, buf = C & 1;
        if (C == TOTC - 1) cp_wait<0>(); else cp_wait<1>();
        __syncthreads();

        // ---- compute: B chunk (lb, kc) ----
        // lb==0 (y0): A limb 0 -> accm, A limb 1 -> accc
        // lb==1 (y1'): A limb 0 -> accc
        const uint32_t bbase = sb + B_OFF + buf * 16384;
        const int lb = c >> 2;          // B limb (0,1)
        const int kc = c & 3;           // k-chunk within the 256-wide limb
        #pragma unroll
        for (int s = 0; s < 4; ++s) {
            uint32_t bf[4][4];
            #pragma unroll
            for (int p = 0; p < 4; ++p)
                ldm_x4(bf[p], bbase + SWZ((WN + p * 16 + nb) * 128 + s * 32 + kbb));

            {   // A limb 0: target = accm if lb==0 else accc
                const uint32_t abase = sb + A_OFF + kc * 16384;
                uint32_t a[2][4];
                #pragma unroll
                for (int f = 0; f < 2; ++f)
                    ldm_x4(a[f], abase + SWZ((WM + f * 16 + ra) * 128 + s * 32 + kba));
                if (lb == 0) {
                    #pragma unroll
                    for (int f = 0; f < 2; ++f)
                        #pragma unroll
                        for (int nf = 0; nf < 8; ++nf)
                            mma16816(accm[f][nf], a[f], &bf[nf >> 1][(nf & 1) * 2]);
                } else {
                    #pragma unroll
                    for (int f = 0; f < 2; ++f)
                        #pragma unroll
                        for (int nf = 0; nf < 8; ++nf)
                            mma16816(accc[f][nf], a[f], &bf[nf >> 1][(nf & 1) * 2]);
                }
            }
            if (lb == 0) {  // A limb 1 vs y0 -> accc
                const uint32_t abase = sb + A_OFF + (4 + kc) * 16384;
                uint32_t a[2][4];
                #pragma unroll
                for (int f = 0; f < 2; ++f)
                    ldm_x4(a[f], abase + SWZ((WM + f * 16 + ra) * 128 + s * 32 + kba));
                #pragma unroll
                for (int f = 0; f < 2; ++f)
                    #pragma unroll
                    for (int nf = 0; nf < 8; ++nf)
                        mma16816(accc[f][nf], a[f], &bf[nf >> 1][(nf & 1) * 2]);
            }
        }

        // ---- tile epilogue: combine limbs, fold into argmax, reset ----
        if (c == NCHUNK - 1) {
            #pragma unroll
            for (int x = 0; x < 4; ++x) {
                const int f = x >> 1, hi = x & 1;
                float bv = bestv[x]; int bi = besti[x];
                #pragma unroll
                for (int nf = 0; nf < 8; ++nf) {
                    int nbase = t * 128 + WN + nf * 8 + (lane & 3) * 2;
                    float v0 = fmaf(accc[f][nf][hi * 2],     CROSS_SCALE, accm[f][nf][hi * 2]);
                    float v1 = fmaf(accc[f][nf][hi * 2 + 1], CROSS_SCALE, accm[f][nf][hi * 2 + 1]);
                    if (v0 > bv) { bv = v0; bi = nbase; }
                    if (v1 > bv) { bv = v1; bi = nbase + 1; }
                    accm[f][nf][hi * 2] = 0.f;     accc[f][nf][hi * 2] = 0.f;
                    accm[f][nf][hi * 2 + 1] = 0.f; accc[f][nf][hi * 2 + 1] = 0.f;
                }
                bestv[x] = bv; besti[x] = bi;
            }
        }
        __syncthreads();

        // ---- prefetch chunk C+2 into buffer buf ----
        if (C + 2 < TOTC) {
            const int C2 = C + 2, t2 = C2 / NCHUNK, c2 = C2 % NCHUNK;
            const __half* gsrc = gBb + (size_t)(t2 * 128) * KS_ + c2 * KC;
            #pragma unroll
            for (int i = 0; i < 4; ++i) {
                int idx = tid + i * 256;
                int r = idx >> 3, q = idx & 7;
                cp_async16(sb + B_OFF + buf * 16384 + SWZ(r * 128 + q * 16),
                           (const char*)(gsrc + (size_t)r * KS_) + q * 16);
            }
            cp_commit();
        }
    }

    // ---- quad reduce: lanes sharing a row (lane^1, lane^2) ----
    #pragma unroll
    for (int x = 0; x < 4; ++x) {
        float v = bestv[x]; int i_ = besti[x];
        #pragma unroll
        for (int o = 1; o <= 2; o <<= 1) {
            float vo = __shfl_xor_sync(0xffffffffu, v, o);
            int   io = __shfl_xor_sync(0xffffffffu, i_, o);
            if (vo > v || (vo == v && io < i_)) { v = vo; i_ = io; }
        }
        bestv[x] = v; besti[x] = i_;
    }

    // ---- cross-warp-column combine via smem (reuse A region) ----
    float* sval = (float*)smem;          // [2][128]
    int*   sidx = (int*)(smem + 1024);   // [2][128]
    __syncthreads();
    if ((lane & 3) == 0) {
        const int col = wid >> 2;
        #pragma unroll
        for (int x = 0; x < 4; ++x) {
            int row = WM + (lane >> 2) + 8 * x;
            sval[col * 128 + row] = bestv[x];
            sidx[col * 128 + row] = besti[x];
        }
    }
    __syncthreads();
    if (tid < 128) {
        float v0 = sval[tid], v1 = sval[128 + tid];
        int   i0 = sidx[tid], i1 = sidx[128 + tid];
        float bv; int bi;
        if (v1 > v0 || (v1 == v0 && i1 < i0)) { bv = v1; bi = i1; }
        else                                  { bv = v0; bi = i0; }
        int n = n0 + tid;
        size_t row = (size_t)b * N_ + n;
        out[row * 2 + 0] = pts[((size_t)b * M_ + bi) * 2 + 0];
        out[row * 2 + 1] = pts[((size_t)b * M_ + bi) * 2 + 1];
        out[(size_t)B_ * N_ * 2 + row] = bv;
    }
}

// ---------------------------------------------------------------------------
extern "C" void kernel_launch(void* const* d_in, const int* in_sizes, int n_in,
                              void* d_out, int out_size) {
    const float* desc_src   = (const float*)d_in[0];
    const float* desc_dst   = (const float*)d_in[1];
    const float* points_dst = (const float*)d_in[2];
    float* out = (float*)d_out;

    int total_rows = B_ * (N_ + M_);
    int nblocks = (total_rows + 7) / 8;
    prep_kernel<<<nblocks, 256>>>(desc_src, desc_dst);

    cudaFuncSetAttribute(match_mma_kernel,
                         cudaFuncAttributeMaxDynamicSharedMemorySize, SMEM_BYTES);
    dim3 grid(N_ / 128, B_);
    match_mma_kernel<<<grid, THREADS, SMEM_BYTES>>>(points_dst, out);
}

// round 14
// speedup vs baseline: 5.6889x; 1.0762x over previous
#include <cuda_runtime.h>
#include <cuda_fp16.h>
#include <cstdint>
#include <math.h>

#define B_ 8
#define N_ 2048
#define M_ 2048
#define D_ 256
#define KS_ 512                  // 2 fp16 limbs x 256
#define KC 64                    // fp16 k per chunk (128-byte rows, SW128)
#define NTILES (M_ / 128)        // 16
#define TSC (NTILES * 4)         // 64 super-chunk steps (tile, kc)
#define THREADS 256

#define A_OFF 0
#define B_OFF 131072             // A: 8 chunks * 16KB = 128KB
#define SMEM_BYTES (131072 + 3 * 32768)   // + 3-deep 32KB super-chunk ring

#define CROSS_SCALE 2.44140625e-4f   // 2^-12

// Split-fp16 operands (pre-normalized rows): [x0 (256) | x1*2^12 (256)]
__device__ __half gA[(size_t)B_ * N_ * KS_];
__device__ __half gBt[(size_t)B_ * M_ * KS_];

#define SWZ(x) ((x) ^ (((x) >> 3) & 0x70))

__device__ __forceinline__ uint32_t smem_u32(const void* p) {
    uint32_t a;
    asm("{ .reg .u64 t; cvta.to.shared.u64 t, %1; cvt.u32.u64 %0, t; }"
        : "=r"(a) : "l"(p));
    return a;
}
__device__ __forceinline__ void cp_async16(uint32_t dst, const void* src) {
    asm volatile("cp.async.cg.shared.global [%0], [%1], 16;"
                 :: "r"(dst), "l"(src) : "memory");
}
__device__ __forceinline__ void cp_commit() {
    asm volatile("cp.async.commit_group;" ::: "memory");
}
template <int N>
__device__ __forceinline__ void cp_wait() {
    asm volatile("cp.async.wait_group %0;" :: "n"(N) : "memory");
}
// Non-trans ldmatrix for BOTH operands (NT pair for mma .row.col), verified.
__device__ __forceinline__ void ldm_x4(uint32_t* r, uint32_t addr) {
    asm volatile("ldmatrix.sync.aligned.m8n8.x4.shared.b16 {%0,%1,%2,%3}, [%4];"
                 : "=r"(r[0]), "=r"(r[1]), "=r"(r[2]), "=r"(r[3]) : "r"(addr));
}
__device__ __forceinline__ void mma16816(float* d, const uint32_t* a,
                                         const uint32_t* b) {
    asm volatile(
        "mma.sync.aligned.m16n8k16.row.col.f32.f16.f16.f32 "
        "{%0,%1,%2,%3}, {%4,%5,%6,%7}, {%8,%9}, {%0,%1,%2,%3};"
        : "+f"(d[0]), "+f"(d[1]), "+f"(d[2]), "+f"(d[3])
        : "r"(a[0]), "r"(a[1]), "r"(a[2]), "r"(a[3]), "r"(b[0]), "r"(b[1]));
}

// ---------------------------------------------------------------------------
// Kernel 1: normalize rows, split fp32 -> 2 fp16 limbs (limb1 scaled 2^12).
// ---------------------------------------------------------------------------
__global__ void prep_kernel(const float* __restrict__ src,
                            const float* __restrict__ dst) {
    int gw = (blockIdx.x * blockDim.x + threadIdx.x) >> 5;
    int lane = threadIdx.x & 31;
    if (gw >= B_ * (N_ + M_)) return;
    bool is_src = gw < B_ * N_;
    int row = is_src ? gw : gw - B_ * N_;
    const float* p = (is_src ? src : dst) + (size_t)row * D_;
    __half* o = (is_src ? gA : gBt) + (size_t)row * KS_;

    float4 v0 = ((const float4*)p)[lane * 2];
    float4 v1 = ((const float4*)p)[lane * 2 + 1];
    float x[8] = {v0.x, v0.y, v0.z, v0.w, v1.x, v1.y, v1.z, v1.w};
    float s = 0.f;
    #pragma unroll
    for (int i = 0; i < 8; i++) s = fmaf(x[i], x[i], s);
    #pragma unroll
    for (int o2 = 16; o2 > 0; o2 >>= 1) s += __shfl_xor_sync(0xffffffffu, s, o2);
    float scale = 1.0f / sqrtf(s);

    __align__(16) __half t0[8], t1[8];
    #pragma unroll
    for (int i = 0; i < 8; i++) {
        float v = x[i] * scale;
        __half h0 = __float2half_rn(v);
        float r = v - __half2float(h0);
        t0[i] = h0;
        t1[i] = __float2half_rn(r * 4096.0f);   // 2^12 pre-scale
    }
    ((uint4*)(o))[lane]       = *(uint4*)t0;
    ((uint4*)(o + 256))[lane] = *(uint4*)t1;
}

// Load one 32KB B super-chunk (y0[kc] | y1[kc]) into ring buffer `buf`.
__device__ __forceinline__ void load_super(uint32_t sb, const __half* gBb,
                                           int t, int kc, int buf, int tid) {
    const uint32_t dstb = sb + B_OFF + buf * 32768;
    #pragma unroll
    for (int i = 0; i < 8; ++i) {
        int idx = tid + i * 256;
        int half = idx >> 10;            // 0: y0 limb, 1: y1 limb
        int rem = idx & 1023;
        int r = rem >> 3, q = rem & 7;
        const __half* src = gBb + (size_t)(t * 128 + r) * KS_ + (half * 4 + kc) * KC;
        cp_async16(dstb + half * 16384 + SWZ(r * 128 + q * 16),
                   (const char*)src + q * 16);
    }
}

// ---------------------------------------------------------------------------
// Kernel 2: fp16 mma.sync GEMM, uniform super-chunks (48 MMA / k16-step),
// 3-deep cp.async ring, one barrier per step, fused argmax + gather.
// ---------------------------------------------------------------------------
__global__ __launch_bounds__(THREADS, 1)
void match_mma_kernel(const float* __restrict__ pts, float* __restrict__ out) {
    extern __shared__ char smem[];
    const uint32_t sb = smem_u32(smem);
    const int tid = threadIdx.x;
    const int wid = tid >> 5;
    const int lane = tid & 31;
    const int b = blockIdx.y;
    const int n0 = blockIdx.x * 128;

    const int WM = (wid & 3) * 32;      // warp m-offset (src rows)
    const int WN = (wid >> 2) * 64;     // warp n-offset (dst cols)

    const __half* gArow = gA + ((size_t)b * N_ + n0) * KS_;
    const __half* gBb   = gBt + (size_t)b * M_ * KS_;

    // ---- prologue: A resident (with SC0's group), SC0, SC1 ----
    #pragma unroll 4
    for (int i = 0; i < 32; ++i) {
        int idx = tid + i * 256;
        int c = idx >> 10, rem = idx & 1023, r = rem >> 3, q = rem & 7;
        cp_async16(sb + A_OFF + c * 16384 + SWZ(r * 128 + q * 16),
                   (const char*)(gArow + (size_t)r * KS_ + c * KC) + q * 16);
    }
    load_super(sb, gBb, 0, 0, 0, tid);
    cp_commit();                          // group: A + SC0
    load_super(sb, gBb, 0, 1, 1, tid);
    cp_commit();                          // group: SC1

    // per-thread ldmatrix lane addressing (non-trans, NT pattern)
    const int ra  = (lane & 7) + ((lane >> 3) & 1) * 8;   // A row within 16
    const int kba = (lane >> 4) * 16;                     // A k-half bytes
    const int nb  = (lane & 7) + ((lane >> 4) & 1) * 8;   // B n-row within 16
    const int kbb = ((lane >> 3) & 1) * 16;               // B k-half bytes

    float accm[2][8][4];   // x0*y0
    float accc[2][8][4];   // x1'*y0 + x0*y1'  (scale 2^-12)
    #pragma unroll
    for (int f = 0; f < 2; ++f)
        #pragma unroll
        for (int nf = 0; nf < 8; ++nf)
            #pragma unroll
            for (int k = 0; k < 4; ++k) { accm[f][nf][k] = 0.f; accc[f][nf][k] = 0.f; }

    float bestv[4] = {-1e30f, -1e30f, -1e30f, -1e30f};
    int   besti[4] = {0, 0, 0, 0};

    for (int SC = 0; SC < TSC; ++SC) {
        const int t = SC >> 2, kc = SC & 3, buf = SC % 3;
        if (SC == TSC - 1) cp_wait<0>(); else cp_wait<1>();
        __syncthreads();

        // prefetch SC+2 into buf (SC+2)%3 (held SC-1; barrier proved it free)
        if (SC + 2 < TSC) {
            const int S2 = SC + 2;
            load_super(sb, gBb, S2 >> 2, S2 & 3, S2 % 3, tid);
            cp_commit();
        }

        // ---- compute super-chunk: uniform 3-pair MMA block ----
        const uint32_t bb0 = sb + B_OFF + buf * 32768;
        const uint32_t bb1 = bb0 + 16384;
        const uint32_t ab0 = sb + A_OFF + kc * 16384;
        const uint32_t ab1 = sb + A_OFF + (4 + kc) * 16384;
        #pragma unroll
        for (int s = 0; s < 4; ++s) {
            uint32_t b0[4][4], b1[4][4];
            #pragma unroll
            for (int p = 0; p < 4; ++p) {
                ldm_x4(b0[p], bb0 + SWZ((WN + p * 16 + nb) * 128 + s * 32 + kbb));
                ldm_x4(b1[p], bb1 + SWZ((WN + p * 16 + nb) * 128 + s * 32 + kbb));
            }
            uint32_t a0[2][4], a1[2][4];
            #pragma unroll
            for (int f = 0; f < 2; ++f) {
                ldm_x4(a0[f], ab0 + SWZ((WM + f * 16 + ra) * 128 + s * 32 + kba));
                ldm_x4(a1[f], ab1 + SWZ((WM + f * 16 + ra) * 128 + s * 32 + kba));
            }
            #pragma unroll
            for (int f = 0; f < 2; ++f)
                #pragma unroll
                for (int nf = 0; nf < 8; ++nf) {
                    const uint32_t* bfr0 = &b0[nf >> 1][(nf & 1) * 2];
                    const uint32_t* bfr1 = &b1[nf >> 1][(nf & 1) * 2];
                    mma16816(accm[f][nf], a0[f], bfr0);
                    mma16816(accc[f][nf], a1[f], bfr0);
                    mma16816(accc[f][nf], a0[f], bfr1);
                }
        }

        // ---- tile epilogue: combine limbs, fold into argmax, reset ----
        if (kc == 3) {
            #pragma unroll
            for (int x = 0; x < 4; ++x) {
                const int f = x >> 1, hi = x & 1;
                float bv = bestv[x]; int bi = besti[x];
                #pragma unroll
                for (int nf = 0; nf < 8; ++nf) {
                    int nbase = t * 128 + WN + nf * 8 + (lane & 3) * 2;
                    float v0 = fmaf(accc[f][nf][hi * 2],     CROSS_SCALE, accm[f][nf][hi * 2]);
                    float v1 = fmaf(accc[f][nf][hi * 2 + 1], CROSS_SCALE, accm[f][nf][hi * 2 + 1]);
                    if (v0 > bv) { bv = v0; bi = nbase; }
                    if (v1 > bv) { bv = v1; bi = nbase + 1; }
                    accm[f][nf][hi * 2] = 0.f;     accc[f][nf][hi * 2] = 0.f;
                    accm[f][nf][hi * 2 + 1] = 0.f; accc[f][nf][hi * 2 + 1] = 0.f;
                }
                bestv[x] = bv; besti[x] = bi;
            }
        }
    }

    // ---- quad reduce: lanes sharing a row (lane^1, lane^2) ----
    #pragma unroll
    for (int x = 0; x < 4; ++x) {
        float v = bestv[x]; int i_ = besti[x];
        #pragma unroll
        for (int o = 1; o <= 2; o <<= 1) {
            float vo = __shfl_xor_sync(0xffffffffu, v, o);
            int   io = __shfl_xor_sync(0xffffffffu, i_, o);
            if (vo > v || (vo == v && io < i_)) { v = vo; i_ = io; }
        }
        bestv[x] = v; besti[x] = i_;
    }

    // ---- cross-warp-column combine via smem (reuse A region) ----
    float* sval = (float*)smem;          // [2][128]
    int*   sidx = (int*)(smem + 1024);   // [2][128]
    __syncthreads();
    if ((lane & 3) == 0) {
        const int col = wid >> 2;
        #pragma unroll
        for (int x = 0; x < 4; ++x) {
            int row = WM + (lane >> 2) + 8 * x;
            sval[col * 128 + row] = bestv[x];
            sidx[col * 128 + row] = besti[x];
        }
    }
    __syncthreads();
    if (tid < 128) {
        float v0 = sval[tid], v1 = sval[128 + tid];
        int   i0 = sidx[tid], i1 = sidx[128 + tid];
        float bv; int bi;
        if (v1 > v0 || (v1 == v0 && i1 < i0)) { bv = v1; bi = i1; }
        else                                  { bv = v0; bi = i0; }
        int n = n0 + tid;
        size_t row = (size_t)b * N_ + n;
        out[row * 2 + 0] = pts[((size_t)b * M_ + bi) * 2 + 0];
        out[row * 2 + 1] = pts[((size_t)b * M_ + bi) * 2 + 1];
        out[(size_t)B_ * N_ * 2 + row] = bv;
    }
}

// ---------------------------------------------------------------------------
extern "C" void kernel_launch(void* const* d_in, const int* in_sizes, int n_in,
                              void* d_out, int out_size) {
    const float* desc_src   = (const float*)d_in[0];
    const float* desc_dst   = (const float*)d_in[1];
    const float* points_dst = (const float*)d_in[2];
    float* out = (float*)d_out;

    int total_rows = B_ * (N_ + M_);
    int nblocks = (total_rows + 7) / 8;
    prep_kernel<<<nblocks, 256>>>(desc_src, desc_dst);

    cudaFuncSetAttribute(match_mma_kernel,
                         cudaFuncAttributeMaxDynamicSharedMemorySize, SMEM_BYTES);
    dim3 grid(N_ / 128, B_);
    match_mma_kernel<<<grid, THREADS, SMEM_BYTES>>>(points_dst, out);
}